// round 10
// baseline (speedup 1.0000x reference)
#include <cuda_runtime.h>
#include <math.h>

#define DIMC 512
#define NHEADS 8
#define HD 64
#define FSZ 56
#define NTOK 3136
#define KTOK 784
#define BATCH 4
#define ATT_SCALE 0.125f
#define LN_EPS 1e-5f
#define POSW 111

// ---------------- scratch ----------------
__device__ float g_bias[NTOK * KTOK];
__device__ float g_q[BATCH * NHEADS * NTOK * HD];
__device__ float g_xr[BATCH * KTOK * DIMC];
__device__ float g_k[BATCH * NHEADS * KTOK * HD];
__device__ float g_v[BATCH * NHEADS * KTOK * HD];
__device__ float g_ao[BATCH * NTOK * DIMC];

// ---------------- tf32 helpers ----------------
__device__ __forceinline__ unsigned f2tf(float f) {
    unsigned u; asm("cvt.rna.tf32.f32 %0, %1;" : "=r"(u) : "f"(f)); return u;
}
__device__ __forceinline__ uint4 tf4(float4 v) {
    uint4 t; t.x = f2tf(v.x); t.y = f2tf(v.y); t.z = f2tf(v.z); t.w = f2tf(v.w); return t;
}
#define MMA8(C, A, B)                                                          \
    asm volatile(                                                              \
        "mma.sync.aligned.m16n8k8.row.col.f32.tf32.tf32.f32 "                  \
        "{%0,%1,%2,%3},{%4,%5,%6,%7},{%8,%9},{%0,%1,%2,%3};"                   \
        : "+f"((C)[0]), "+f"((C)[1]), "+f"((C)[2]), "+f"((C)[3])               \
        : "r"((A)[0]), "r"((A)[1]), "r"((A)[2]), "r"((A)[3]),                  \
          "r"((B)[0]), "r"((B)[1]))

#define APAD 136
#define BPAD 72
#define ATILE (16 * APAD)
#define BTILE (16 * BPAD)

// Fragment compute for one 16-k tile: As[16][APAD] (k,m), Bs[16][BPAD] (k,n).
__device__ __forceinline__ void mma_tile16(const unsigned* __restrict__ As,
                                           const unsigned* __restrict__ Bs,
                                           float c[2][4][4], int wm, int wn,
                                           int g, int tig) {
#pragma unroll
    for (int kk = 0; kk < 16; kk += 8) {
        unsigned a[2][4], bf[4][2];
#pragma unroll
        for (int mt = 0; mt < 2; mt++) {
            int mr = wm * 32 + mt * 16 + g;
            a[mt][0] = As[(kk + tig) * APAD + mr];
            a[mt][1] = As[(kk + tig) * APAD + mr + 8];
            a[mt][2] = As[(kk + tig + 4) * APAD + mr];
            a[mt][3] = As[(kk + tig + 4) * APAD + mr + 8];
        }
#pragma unroll
        for (int nt = 0; nt < 4; nt++) {
            int nc = wn * 32 + nt * 8 + g;
            bf[nt][0] = Bs[(kk + tig) * BPAD + nc];
            bf[nt][1] = Bs[(kk + tig + 4) * BPAD + nc];
        }
#pragma unroll
        for (int mt = 0; mt < 2; mt++)
#pragma unroll
            for (int nt = 0; nt < 4; nt++) MMA8(c[mt][nt], a[mt], bf[nt]);
    }
}

// ---------------- bias precompute (vectorized: 2 elems/thread) ----------------
__global__ void bias_kernel(const float* __restrict__ pos, const int* __restrict__ rel) {
    int i = blockIdx.x * 256 + threadIdx.x;          // pair index
    if (i >= NTOK * KTOK / 2) return;
    int e = 2 * i;
    int n = e / KTOK, m = e % KTOK;
    int4 r = *(const int4*)&rel[((long long)n * NTOK + m) * 2];
    float2 o;
    o.x = pos[r.x * POSW + r.y];
    o.y = pos[r.z * POSW + r.w];
    *(float2*)&g_bias[e] = o;
}

// ======================= fused Q + conv projections =======================
// grid (8, 32, 4): y<25 -> Q GEMM (M=3136,N=512,K=512); y>=25 -> conv GEMM
// (M=784,N=512,K=2048). Double-buffered smem, register prefetch, 1 sync/iter.
__device__ __forceinline__ void q_body(const float* __restrict__ xb,
                                       const float* __restrict__ Wq,
                                       unsigned* As, unsigned* Bs,
                                       int b, int m0, int n0) {
    int tid = threadIdx.x, lane = tid & 31, warp = tid >> 5;
    int g = lane >> 2, tig = lane & 3;
    int wm = warp >> 1, wn = warp & 1;
    float c[2][4][4] = {};
    int krA = tid >> 5, c4A = (tid & 31) * 4;        // A rows krA, krA+8
    int krB = tid >> 4, c4B = (tid & 15) * 4;
    bool mv = (m0 + c4A) < NTOK;
    float4 ra0, ra1, rb;
    {
        const float* ap = xb + (size_t)krA * NTOK + m0 + c4A;
        ra0 = mv ? *(const float4*)ap : make_float4(0, 0, 0, 0);
        ra1 = mv ? *(const float4*)(ap + 8 * (size_t)NTOK) : make_float4(0, 0, 0, 0);
        rb = *(const float4*)&Wq[(size_t)krB * DIMC + n0 + c4B];
    }
    *(uint4*)&As[krA * APAD + c4A] = tf4(ra0);
    *(uint4*)&As[(krA + 8) * APAD + c4A] = tf4(ra1);
    *(uint4*)&Bs[krB * BPAD + c4B] = tf4(rb);
    __syncthreads();
    for (int k0 = 0; k0 < DIMC; k0 += 16) {
        int cur = (k0 >> 4) & 1;
        unsigned* Ac = As + cur * ATILE;
        unsigned* Bc = Bs + cur * BTILE;
        bool more = (k0 + 16) < DIMC;
        if (more) {
            const float* ap = xb + (size_t)(k0 + 16 + krA) * NTOK + m0 + c4A;
            ra0 = mv ? *(const float4*)ap : make_float4(0, 0, 0, 0);
            ra1 = mv ? *(const float4*)(ap + 8 * (size_t)NTOK) : make_float4(0, 0, 0, 0);
            rb = *(const float4*)&Wq[(size_t)(k0 + 16 + krB) * DIMC + n0 + c4B];
        }
        mma_tile16(Ac, Bc, c, wm, wn, g, tig);
        if (more) {
            unsigned* An = As + (1 - cur) * ATILE;
            unsigned* Bn = Bs + (1 - cur) * BTILE;
            *(uint4*)&An[krA * APAD + c4A] = tf4(ra0);
            *(uint4*)&An[(krA + 8) * APAD + c4A] = tf4(ra1);
            *(uint4*)&Bn[krB * BPAD + c4B] = tf4(rb);
        }
        __syncthreads();
    }
#pragma unroll
    for (int mt = 0; mt < 2; mt++) {
        int r1 = m0 + wm * 32 + mt * 16 + g, r2 = r1 + 8;
#pragma unroll
        for (int nt = 0; nt < 4; nt++) {
            int n = n0 + wn * 32 + nt * 8 + tig * 2;
            int h = n >> 6, d = n & 63;
            if (r1 < NTOK)
                *(float2*)&g_q[(((size_t)b * NHEADS + h) * NTOK + r1) * HD + d] =
                    make_float2(c[mt][nt][0], c[mt][nt][1]);
            if (r2 < NTOK)
                *(float2*)&g_q[(((size_t)b * NHEADS + h) * NTOK + r2) * HD + d] =
                    make_float2(c[mt][nt][2], c[mt][nt][3]);
        }
    }
}

__device__ __forceinline__ void conv_body(const float* __restrict__ xb,
                                          const float* __restrict__ Wsr,
                                          const float* __restrict__ b_sr,
                                          unsigned* As, unsigned* Bs,
                                          int b, int m0, int n0) {
    int tid = threadIdx.x, lane = tid & 31, warp = tid >> 5;
    int g = lane >> 2, tig = lane & 3;
    int wm = warp >> 1, wn = warp & 1;
    float c[2][4][4] = {};
    int krA = tid >> 5, c4A = (tid & 31) * 4;        // A rows krA, krA+8, cols c4A..+3
    int nrB = tid >> 2, kc4B = (tid & 3) * 4;
    // precompute spatial offsets for the 4 m-columns (fixed per thread)
    int moff[4]; bool mval[4];
#pragma unroll
    for (int q = 0; q < 4; q++) {
        int m = m0 + c4A + q;
        mval[q] = m < KTOK;
        int ph = m / 28, pw = m - ph * 28;
        moff[q] = mval[q] ? (2 * ph * FSZ + 2 * pw) : 0;
    }
    float a0[4], a1[4]; float4 rb;
    auto loadA = [&](int k0, float* d0, float* d1) {
        int k = k0 + krA;                            // rows krA and krA+8
        int ii = k >> 2, kh = (k >> 1) & 1, kw = k & 1;
        const float* xp = xb + (size_t)ii * NTOK + kh * FSZ + kw;
        int k2 = k + 8;
        int ii2 = k2 >> 2, kh2 = (k2 >> 1) & 1, kw2 = k2 & 1;
        const float* xp2 = xb + (size_t)ii2 * NTOK + kh2 * FSZ + kw2;
#pragma unroll
        for (int q = 0; q < 4; q++) {
            d0[q] = mval[q] ? xp[moff[q]] : 0.f;
            d1[q] = mval[q] ? xp2[moff[q]] : 0.f;
        }
    };
    loadA(0, a0, a1);
    rb = *(const float4*)&Wsr[(size_t)(n0 + nrB) * 2048 + kc4B];
    {
        unsigned* Ad = As;
#pragma unroll
        for (int q = 0; q < 4; q++) {
            Ad[krA * APAD + c4A + q] = f2tf(a0[q]);
            Ad[(krA + 8) * APAD + c4A + q] = f2tf(a1[q]);
        }
        Bs[(kc4B + 0) * BPAD + nrB] = f2tf(rb.x);
        Bs[(kc4B + 1) * BPAD + nrB] = f2tf(rb.y);
        Bs[(kc4B + 2) * BPAD + nrB] = f2tf(rb.z);
        Bs[(kc4B + 3) * BPAD + nrB] = f2tf(rb.w);
    }
    __syncthreads();
    for (int k0 = 0; k0 < 2048; k0 += 16) {
        int cur = (k0 >> 4) & 1;
        unsigned* Ac = As + cur * ATILE;
        unsigned* Bc = Bs + cur * BTILE;
        bool more = (k0 + 16) < 2048;
        if (more) {
            loadA(k0 + 16, a0, a1);
            rb = *(const float4*)&Wsr[(size_t)(n0 + nrB) * 2048 + k0 + 16 + kc4B];
        }
        mma_tile16(Ac, Bc, c, wm, wn, g, tig);
        if (more) {
            unsigned* An = As + (1 - cur) * ATILE;
            unsigned* Bn = Bs + (1 - cur) * BTILE;
#pragma unroll
            for (int q = 0; q < 4; q++) {
                An[krA * APAD + c4A + q] = f2tf(a0[q]);
                An[(krA + 8) * APAD + c4A + q] = f2tf(a1[q]);
            }
            Bn[(kc4B + 0) * BPAD + nrB] = f2tf(rb.x);
            Bn[(kc4B + 1) * BPAD + nrB] = f2tf(rb.y);
            Bn[(kc4B + 2) * BPAD + nrB] = f2tf(rb.z);
            Bn[(kc4B + 3) * BPAD + nrB] = f2tf(rb.w);
        }
        __syncthreads();
    }
#pragma unroll
    for (int mt = 0; mt < 2; mt++) {
        int r1 = m0 + wm * 32 + mt * 16 + g, r2 = r1 + 8;
#pragma unroll
        for (int nt = 0; nt < 4; nt++) {
            int n = n0 + wn * 32 + nt * 8 + tig * 2;
            float2 bb = *(const float2*)&b_sr[n];
            if (r1 < KTOK)
                *(float2*)&g_xr[((size_t)b * KTOK + r1) * DIMC + n] =
                    make_float2(c[mt][nt][0] + bb.x, c[mt][nt][1] + bb.y);
            if (r2 < KTOK)
                *(float2*)&g_xr[((size_t)b * KTOK + r2) * DIMC + n] =
                    make_float2(c[mt][nt][2] + bb.x, c[mt][nt][3] + bb.y);
        }
    }
}

__global__ __launch_bounds__(256) void gemm_qc(const float* __restrict__ x,
                                               const float* __restrict__ Wq,
                                               const float* __restrict__ Wsr,
                                               const float* __restrict__ b_sr) {
    __shared__ unsigned As[2 * ATILE];
    __shared__ unsigned Bs[2 * BTILE];
    int b = blockIdx.z;
    const float* xb = x + (size_t)b * DIMC * NTOK;
    if (blockIdx.y < 25)
        q_body(xb, Wq, As, Bs, b, blockIdx.y * 128, blockIdx.x * 64);
    else
        conv_body(xb, Wsr, b_sr, As, Bs, b, (blockIdx.y - 25) * 128, blockIdx.x * 64);
}

// ---------------- LayerNorm ----------------
__global__ void ln_kernel(const float* __restrict__ gamma, const float* __restrict__ beta) {
    int row = blockIdx.x;
    float* p = g_xr + (long long)row * DIMC;
    int t = threadIdx.x;
    float v0 = p[t], v1 = p[t + 256];
    float s = v0 + v1, sq = v0 * v0 + v1 * v1;
#pragma unroll
    for (int o = 16; o > 0; o >>= 1) {
        s += __shfl_xor_sync(0xffffffffu, s, o);
        sq += __shfl_xor_sync(0xffffffffu, sq, o);
    }
    __shared__ float rs_[8], rq_[8];
    int lane = t & 31, w = t >> 5;
    if (lane == 0) { rs_[w] = s; rq_[w] = sq; }
    __syncthreads();
    if (t == 0) {
        float S = 0.f, Q = 0.f;
#pragma unroll
        for (int i = 0; i < 8; i++) { S += rs_[i]; Q += rq_[i]; }
        rs_[0] = S; rq_[0] = Q;
    }
    __syncthreads();
    float mu = rs_[0] * (1.f / 512.f);
    float var = rq_[0] * (1.f / 512.f) - mu * mu;
    float inv = rsqrtf(var + LN_EPS);
    p[t] = (v0 - mu) * inv * gamma[t] + beta[t];
    p[t + 256] = (v1 - mu) * inv * gamma[t + 256] + beta[t + 256];
}

// ---------------- GEMM KV (tf32, double-buffered): M=784, N=1024, K=512 ----------------
__global__ __launch_bounds__(256) void gemm_kv(const float* __restrict__ Wkv) {
    __shared__ unsigned As[2 * ATILE];
    __shared__ unsigned Bs[2 * BTILE];
    int b = blockIdx.z, m0 = blockIdx.y * 128, n0 = blockIdx.x * 64;
    int tid = threadIdx.x, lane = tid & 31, warp = tid >> 5;
    int g = lane >> 2, tig = lane & 3;
    int wm = warp >> 1, wn = warp & 1;
    const float* A = g_xr + (size_t)b * KTOK * DIMC;
    float c[2][4][4] = {};
    int mrA = tid >> 2, kc4A = (tid & 3) * 4;        // A rows mrA, mrA+64 (transpose store)
    int krB = tid >> 4, c4B = (tid & 15) * 4;
    bool mv1 = (m0 + mrA) < KTOK, mv2 = (m0 + mrA + 64) < KTOK;
    float4 ra0, ra1, rb;
    auto loadT = [&](int k0) {
        const float* ap = A + (size_t)(m0 + mrA) * DIMC + k0 + kc4A;
        ra0 = mv1 ? *(const float4*)ap : make_float4(0, 0, 0, 0);
        ra1 = mv2 ? *(const float4*)(ap + 64 * (size_t)DIMC) : make_float4(0, 0, 0, 0);
        rb = *(const float4*)&Wkv[(size_t)(k0 + krB) * 1024 + n0 + c4B];
    };
    auto storeT = [&](unsigned* Ad, unsigned* Bd) {
        Ad[(kc4A + 0) * APAD + mrA] = f2tf(ra0.x);
        Ad[(kc4A + 1) * APAD + mrA] = f2tf(ra0.y);
        Ad[(kc4A + 2) * APAD + mrA] = f2tf(ra0.z);
        Ad[(kc4A + 3) * APAD + mrA] = f2tf(ra0.w);
        Ad[(kc4A + 0) * APAD + mrA + 64] = f2tf(ra1.x);
        Ad[(kc4A + 1) * APAD + mrA + 64] = f2tf(ra1.y);
        Ad[(kc4A + 2) * APAD + mrA + 64] = f2tf(ra1.z);
        Ad[(kc4A + 3) * APAD + mrA + 64] = f2tf(ra1.w);
        *(uint4*)&Bd[krB * BPAD + c4B] = tf4(rb);
    };
    loadT(0); storeT(As, Bs);
    __syncthreads();
    for (int k0 = 0; k0 < DIMC; k0 += 16) {
        int cur = (k0 >> 4) & 1;
        bool more = (k0 + 16) < DIMC;
        if (more) loadT(k0 + 16);
        mma_tile16(As + cur * ATILE, Bs + cur * BTILE, c, wm, wn, g, tig);
        if (more) storeT(As + (1 - cur) * ATILE, Bs + (1 - cur) * BTILE);
        __syncthreads();
    }
#pragma unroll
    for (int mt = 0; mt < 2; mt++) {
        int r1 = m0 + wm * 32 + mt * 16 + g, r2 = r1 + 8;
#pragma unroll
        for (int nt = 0; nt < 4; nt++) {
            int n = n0 + wn * 32 + nt * 8 + tig * 2;
            int d = n >> 4, h = (n >> 1) & 7;
            if (r1 < KTOK) {
                size_t dst = (((size_t)b * NHEADS + h) * KTOK + r1) * HD + d;
                g_k[dst] = c[mt][nt][0];
                g_v[dst] = c[mt][nt][1];
            }
            if (r2 < KTOK) {
                size_t dst = (((size_t)b * NHEADS + h) * KTOK + r2) * HD + d;
                g_k[dst] = c[mt][nt][2];
                g_v[dst] = c[mt][nt][3];
            }
        }
    }
}

// ---------------- fused attention (tf32 MMA flash) — unchanged from R8 ----------------
__global__ __launch_bounds__(256, 2) void attn_kernel() {
    extern __shared__ __align__(16) unsigned smu[];
    unsigned* Ks = smu;                       // 112*68
    unsigned* Vs = smu + 7616;                // 112*72
    unsigned* Ps = Vs + 8064;                 // 64*132
    float* redm = (float*)(Ps + 8448);        // 128
    float* reds = redm + 128;                 // 128

    int bh = blockIdx.y, row0 = blockIdx.x * 64;
    int tid = threadIdx.x, lane = tid & 31, warp = tid >> 5;
    int g = lane >> 2, tig = lane & 3;
    int wm = warp & 3, wn = warp >> 2;

    const float* qb = g_q + (size_t)bh * NTOK * HD;
    const float* kb = g_k + (size_t)bh * KTOK * HD;
    const float* vb = g_v + (size_t)bh * KTOK * HD;

    int r1 = wm * 16 + g, r2 = r1 + 8;

    unsigned aq[8][4];
    {
        const float* q1 = qb + (size_t)(row0 + r1) * HD;
        const float* q2 = qb + (size_t)(row0 + r2) * HD;
#pragma unroll
        for (int ks = 0; ks < 8; ks++) {
            aq[ks][0] = f2tf(q1[ks * 8 + tig]);
            aq[ks][1] = f2tf(q2[ks * 8 + tig]);
            aq[ks][2] = f2tf(q1[ks * 8 + tig + 4]);
            aq[ks][3] = f2tf(q2[ks * 8 + tig + 4]);
        }
    }
    float run_max1 = -INFINITY, run_max2 = -INFINITY;
    float run_sum1 = 0.f, run_sum2 = 0.f;
    float c_o[4][4] = {};

    for (int t = 0; t < 7; t++) {
        int m0 = t * 112;
        __syncthreads();
        for (int e = tid; e < 112 * 16; e += 256) {
            int mr = e >> 4, d4 = (e & 15) * 4;
            float4 k4 = *(const float4*)&kb[(size_t)(m0 + mr) * HD + d4];
            unsigned* kd = &Ks[mr * 68 + d4];
            kd[0] = f2tf(k4.x); kd[1] = f2tf(k4.y); kd[2] = f2tf(k4.z); kd[3] = f2tf(k4.w);
            float4 v4 = *(const float4*)&vb[(size_t)(m0 + mr) * HD + d4];
            unsigned* vd = &Vs[mr * 72 + d4];
            vd[0] = f2tf(v4.x); vd[1] = f2tf(v4.y); vd[2] = f2tf(v4.z); vd[3] = f2tf(v4.w);
        }
        __syncthreads();

        float cs[7][4] = {};
#pragma unroll
        for (int ks = 0; ks < 8; ks++) {
#pragma unroll
            for (int nt = 0; nt < 7; nt++) {
                int n = wn * 56 + nt * 8 + g;
                unsigned bk[2];
                bk[0] = Ks[n * 68 + ks * 8 + tig];
                bk[1] = Ks[n * 68 + ks * 8 + tig + 4];
                MMA8(cs[nt], aq[ks], bk);
            }
        }
        float p1[14], p2[14];
        float mx1 = -INFINITY, mx2 = -INFINITY;
#pragma unroll
        for (int nt = 0; nt < 7; nt++) {
            int col = m0 + wn * 56 + nt * 8 + tig * 2;
            float2 b1 = *(const float2*)&g_bias[(size_t)(row0 + r1) * KTOK + col];
            float2 b2 = *(const float2*)&g_bias[(size_t)(row0 + r2) * KTOK + col];
            p1[2 * nt]     = cs[nt][0] * ATT_SCALE + b1.x;
            p1[2 * nt + 1] = cs[nt][1] * ATT_SCALE + b1.y;
            p2[2 * nt]     = cs[nt][2] * ATT_SCALE + b2.x;
            p2[2 * nt + 1] = cs[nt][3] * ATT_SCALE + b2.y;
            mx1 = fmaxf(mx1, fmaxf(p1[2 * nt], p1[2 * nt + 1]));
            mx2 = fmaxf(mx2, fmaxf(p2[2 * nt], p2[2 * nt + 1]));
        }
        mx1 = fmaxf(mx1, __shfl_xor_sync(0xffffffffu, mx1, 1));
        mx1 = fmaxf(mx1, __shfl_xor_sync(0xffffffffu, mx1, 2));
        mx2 = fmaxf(mx2, __shfl_xor_sync(0xffffffffu, mx2, 1));
        mx2 = fmaxf(mx2, __shfl_xor_sync(0xffffffffu, mx2, 2));
        if (tig == 0) { redm[wn * 64 + r1] = mx1; redm[wn * 64 + r2] = mx2; }
        __syncthreads();
        float tm1 = fmaxf(redm[r1], redm[64 + r1]);
        float tm2 = fmaxf(redm[r2], redm[64 + r2]);
        float nm1 = fmaxf(run_max1, tm1), nm2 = fmaxf(run_max2, tm2);
        float co1 = __expf(run_max1 - nm1), co2 = __expf(run_max2 - nm2);
        run_max1 = nm1; run_max2 = nm2;
        float s1 = 0.f, s2 = 0.f;
#pragma unroll
        for (int i = 0; i < 14; i++) {
            p1[i] = __expf(p1[i] - nm1); s1 += p1[i];
            p2[i] = __expf(p2[i] - nm2); s2 += p2[i];
        }
        s1 += __shfl_xor_sync(0xffffffffu, s1, 1);
        s1 += __shfl_xor_sync(0xffffffffu, s1, 2);
        s2 += __shfl_xor_sync(0xffffffffu, s2, 1);
        s2 += __shfl_xor_sync(0xffffffffu, s2, 2);
        if (tig == 0) { reds[wn * 64 + r1] = s1; reds[wn * 64 + r2] = s2; }
#pragma unroll
        for (int nt = 0; nt < 7; nt++) {
            int col = wn * 56 + nt * 8 + tig * 2;
            uint2 w1 = make_uint2(f2tf(p1[2 * nt]), f2tf(p1[2 * nt + 1]));
            uint2 w2 = make_uint2(f2tf(p2[2 * nt]), f2tf(p2[2 * nt + 1]));
            *(uint2*)&Ps[r1 * 132 + col] = w1;
            *(uint2*)&Ps[r2 * 132 + col] = w2;
        }
#pragma unroll
        for (int nt = 0; nt < 4; nt++) {
            c_o[nt][0] *= co1; c_o[nt][1] *= co1;
            c_o[nt][2] *= co2; c_o[nt][3] *= co2;
        }
        __syncthreads();
        run_sum1 = run_sum1 * co1 + reds[r1] + reds[64 + r1];
        run_sum2 = run_sum2 * co2 + reds[r2] + reds[64 + r2];
#pragma unroll
        for (int ks = 0; ks < 14; ks++) {
            unsigned ap[4];
            ap[0] = Ps[r1 * 132 + ks * 8 + tig];
            ap[1] = Ps[r2 * 132 + ks * 8 + tig];
            ap[2] = Ps[r1 * 132 + ks * 8 + tig + 4];
            ap[3] = Ps[r2 * 132 + ks * 8 + tig + 4];
#pragma unroll
            for (int nt = 0; nt < 4; nt++) {
                int n = wn * 32 + nt * 8 + g;
                unsigned bv[2];
                bv[0] = Vs[(ks * 8 + tig) * 72 + n];
                bv[1] = Vs[(ks * 8 + tig + 4) * 72 + n];
                MMA8(c_o[nt], ap, bv);
            }
        }
    }
    int b = bh >> 3, h = bh & 7;
    float i1 = 1.f / run_sum1, i2 = 1.f / run_sum2;
#pragma unroll
    for (int nt = 0; nt < 4; nt++) {
        int d = h * HD + wn * 32 + nt * 8 + tig * 2;
        *(float2*)&g_ao[((size_t)b * NTOK + row0 + r1) * DIMC + d] =
            make_float2(c_o[nt][0] * i1, c_o[nt][1] * i1);
        *(float2*)&g_ao[((size_t)b * NTOK + row0 + r2) * DIMC + d] =
            make_float2(c_o[nt][2] * i2, c_o[nt][3] * i2);
    }
}

// ---------------- GEMM out (tf32, double-buffered): [12544,512]@[512,512] ----------------
__global__ __launch_bounds__(256) void gemm_out(const float* __restrict__ Wp,
                                                const float* __restrict__ bp,
                                                float* __restrict__ out) {
    __shared__ unsigned As[2 * ATILE];
    __shared__ unsigned Bs[2 * BTILE];
    int m0 = blockIdx.y * 128, n0 = blockIdx.x * 64;
    int tid = threadIdx.x, lane = tid & 31, warp = tid >> 5;
    int g = lane >> 2, tig = lane & 3;
    int wm = warp >> 1, wn = warp & 1;
    float c[2][4][4] = {};
    int mrA = tid >> 2, kc4A = (tid & 3) * 4;
    int krB = tid >> 4, c4B = (tid & 15) * 4;
    float4 ra0, ra1, rb;
    auto loadT = [&](int k0) {
        const float* ap = g_ao + (size_t)(m0 + mrA) * DIMC + k0 + kc4A;
        ra0 = *(const float4*)ap;
        ra1 = *(const float4*)(ap + 64 * (size_t)DIMC);
        rb = *(const float4*)&Wp[(size_t)(k0 + krB) * DIMC + n0 + c4B];
    };
    auto storeT = [&](unsigned* Ad, unsigned* Bd) {
        Ad[(kc4A + 0) * APAD + mrA] = f2tf(ra0.x);
        Ad[(kc4A + 1) * APAD + mrA] = f2tf(ra0.y);
        Ad[(kc4A + 2) * APAD + mrA] = f2tf(ra0.z);
        Ad[(kc4A + 3) * APAD + mrA] = f2tf(ra0.w);
        Ad[(kc4A + 0) * APAD + mrA + 64] = f2tf(ra1.x);
        Ad[(kc4A + 1) * APAD + mrA + 64] = f2tf(ra1.y);
        Ad[(kc4A + 2) * APAD + mrA + 64] = f2tf(ra1.z);
        Ad[(kc4A + 3) * APAD + mrA + 64] = f2tf(ra1.w);
        *(uint4*)&Bd[krB * BPAD + c4B] = tf4(rb);
    };
    loadT(0); storeT(As, Bs);
    __syncthreads();
    for (int k0 = 0; k0 < DIMC; k0 += 16) {
        int cur = (k0 >> 4) & 1;
        bool more = (k0 + 16) < DIMC;
        if (more) loadT(k0 + 16);
        mma_tile16(As + cur * ATILE, Bs + cur * BTILE, c, wm, wn, g, tig);
        if (more) storeT(As + (1 - cur) * ATILE, Bs + (1 - cur) * BTILE);
        __syncthreads();
    }
#pragma unroll
    for (int mt = 0; mt < 2; mt++) {
        int r1 = m0 + wm * 32 + mt * 16 + g, r2 = r1 + 8;
        int b1 = r1 / NTOK, n1 = r1 - b1 * NTOK;
        int b2 = r2 / NTOK, n2 = r2 - b2 * NTOK;
#pragma unroll
        for (int nt = 0; nt < 4; nt++) {
            int cc = n0 + wn * 32 + nt * 8 + tig * 2;
            float bb0 = bp[cc], bb1 = bp[cc + 1];
            out[((size_t)b1 * DIMC + cc) * NTOK + n1] = c[mt][nt][0] + bb0;
            out[((size_t)b1 * DIMC + cc + 1) * NTOK + n1] = c[mt][nt][1] + bb1;
            out[((size_t)b2 * DIMC + cc) * NTOK + n2] = c[mt][nt][2] + bb0;
            out[((size_t)b2 * DIMC + cc + 1) * NTOK + n2] = c[mt][nt][3] + bb1;
        }
    }
}

// ---------------- launch ----------------
extern "C" void kernel_launch(void* const* d_in, const int* in_sizes, int n_in,
                              void* d_out, int out_size) {
    const float* x     = (const float*)d_in[0];
    const float* Wq    = (const float*)d_in[1];
    const float* Wkv   = (const float*)d_in[2];
    const float* Wsr   = (const float*)d_in[3];
    const float* b_sr  = (const float*)d_in[4];
    const float* gamma = (const float*)d_in[5];
    const float* beta  = (const float*)d_in[6];
    const float* Wp    = (const float*)d_in[7];
    const float* bp    = (const float*)d_in[8];
    const float* pos   = (const float*)d_in[9];
    const int*   rel   = (const int*)d_in[10];
    float* out = (float*)d_out;

    const int ATT_SMEM = (7616 + 8064 + 8448 + 256) * 4;  // 97,536 B
    cudaFuncSetAttribute(attn_kernel, cudaFuncAttributeMaxDynamicSharedMemorySize, ATT_SMEM);

    bias_kernel<<<(NTOK * KTOK / 2 + 255) / 256, 256>>>(pos, rel);
    gemm_qc<<<dim3(8, 32, BATCH), 256>>>(x, Wq, Wsr, b_sr);
    ln_kernel<<<BATCH * KTOK, 256>>>(gamma, beta);
    gemm_kv<<<dim3(16, 7, BATCH), 256>>>(Wkv);
    attn_kernel<<<dim3(49, 32), 256, ATT_SMEM>>>();
    gemm_out<<<dim3(8, 98, 1), 256>>>(Wp, bp, out);
}

// round 11
// speedup vs baseline: 1.0030x; 1.0030x over previous
#include <cuda_runtime.h>
#include <math.h>

#define DIMC 512
#define NHEADS 8
#define HD 64
#define FSZ 56
#define NTOK 3136
#define KTOK 784
#define BATCH 4
#define ATT_SCALE 0.125f
#define LN_EPS 1e-5f
#define POSW 111

// ---------------- scratch ----------------
__device__ float g_bias[NTOK * KTOK];
__device__ float g_q[BATCH * NHEADS * NTOK * HD];
__device__ float g_xr[BATCH * KTOK * DIMC];
__device__ float g_k[BATCH * NHEADS * KTOK * HD];
__device__ float g_v[BATCH * NHEADS * KTOK * HD];
__device__ float g_ao[BATCH * NTOK * DIMC];

// ---------------- tf32 helpers ----------------
__device__ __forceinline__ unsigned f2tf(float f) {
    unsigned u; asm("cvt.rna.tf32.f32 %0, %1;" : "=r"(u) : "f"(f)); return u;
}
__device__ __forceinline__ uint4 tf4(float4 v) {
    uint4 t; t.x = f2tf(v.x); t.y = f2tf(v.y); t.z = f2tf(v.z); t.w = f2tf(v.w); return t;
}
#define MMA8(C, A, B)                                                          \
    asm volatile(                                                              \
        "mma.sync.aligned.m16n8k8.row.col.f32.tf32.tf32.f32 "                  \
        "{%0,%1,%2,%3},{%4,%5,%6,%7},{%8,%9},{%0,%1,%2,%3};"                   \
        : "+f"((C)[0]), "+f"((C)[1]), "+f"((C)[2]), "+f"((C)[3])               \
        : "r"((A)[0]), "r"((A)[1]), "r"((A)[2]), "r"((A)[3]),                  \
          "r"((B)[0]), "r"((B)[1]))

// 128x128 block: As[16][136] (k, m=128), Bs[16][136] (k, n=128)
#define TPAD 136

// warp = 32m x 64n: wm in 0..3, wn in 0..1. 1.5 LDS.32 per MMA.
__device__ __forceinline__ void mma_tile16w(const unsigned* __restrict__ As,
                                            const unsigned* __restrict__ Bs,
                                            float c[2][8][4], int wm, int wn,
                                            int g, int tig) {
#pragma unroll
    for (int kk = 0; kk < 16; kk += 8) {
        unsigned a[2][4], bf[8][2];
#pragma unroll
        for (int mt = 0; mt < 2; mt++) {
            int mr = wm * 32 + mt * 16 + g;
            a[mt][0] = As[(kk + tig) * TPAD + mr];
            a[mt][1] = As[(kk + tig) * TPAD + mr + 8];
            a[mt][2] = As[(kk + tig + 4) * TPAD + mr];
            a[mt][3] = As[(kk + tig + 4) * TPAD + mr + 8];
        }
#pragma unroll
        for (int nt = 0; nt < 8; nt++) {
            int nc = wn * 64 + nt * 8 + g;
            bf[nt][0] = Bs[(kk + tig) * TPAD + nc];
            bf[nt][1] = Bs[(kk + tig + 4) * TPAD + nc];
        }
#pragma unroll
        for (int mt = 0; mt < 2; mt++)
#pragma unroll
            for (int nt = 0; nt < 8; nt++) MMA8(c[mt][nt], a[mt], bf[nt]);
    }
}

// ---------------- bias precompute (2 elems/thread) ----------------
__global__ void bias_kernel(const float* __restrict__ pos, const int* __restrict__ rel) {
    int i = blockIdx.x * 256 + threadIdx.x;
    if (i >= NTOK * KTOK / 2) return;
    int e = 2 * i;
    int n = e / KTOK, m = e % KTOK;
    int4 r = *(const int4*)&rel[((long long)n * NTOK + m) * 2];
    float2 o;
    o.x = pos[r.x * POSW + r.y];
    o.y = pos[r.z * POSW + r.w];
    *(float2*)&g_bias[e] = o;
}

// ======================= fused Q + conv projections =======================
// grid (4, 32, 4): y<25 -> Q (M=3136,N=512,K=512); y>=25 -> conv (M=784,N=512,K=2048)
__device__ __forceinline__ void q_body(const float* __restrict__ xb,
                                       const float* __restrict__ Wq,
                                       unsigned* As, unsigned* Bs,
                                       int b, int m0, int n0) {
    int tid = threadIdx.x, lane = tid & 31, warp = tid >> 5;
    int g = lane >> 2, tig = lane & 3;
    int wm = warp >> 1, wn = warp & 1;
    float c[2][8][4] = {};
    int kr = tid >> 5, c4 = (tid & 31) * 4;          // rows kr, kr+8
    bool mv = (m0 + c4) < NTOK;
    for (int k0 = 0; k0 < DIMC; k0 += 16) {
        {
            const float* ap = xb + (size_t)(k0 + kr) * NTOK + m0 + c4;
            float4 a0 = mv ? *(const float4*)ap : make_float4(0, 0, 0, 0);
            float4 a1 = mv ? *(const float4*)(ap + 8 * (size_t)NTOK) : make_float4(0, 0, 0, 0);
            *(uint4*)&As[kr * TPAD + c4] = tf4(a0);
            *(uint4*)&As[(kr + 8) * TPAD + c4] = tf4(a1);
            const float* bp = Wq + (size_t)(k0 + kr) * DIMC + n0 + c4;
            *(uint4*)&Bs[kr * TPAD + c4] = tf4(*(const float4*)bp);
            *(uint4*)&Bs[(kr + 8) * TPAD + c4] = tf4(*(const float4*)(bp + 8 * (size_t)DIMC));
        }
        __syncthreads();
        mma_tile16w(As, Bs, c, wm, wn, g, tig);
        __syncthreads();
    }
#pragma unroll
    for (int mt = 0; mt < 2; mt++) {
        int r1 = m0 + wm * 32 + mt * 16 + g, r2 = r1 + 8;
#pragma unroll
        for (int nt = 0; nt < 8; nt++) {
            int n = n0 + wn * 64 + nt * 8 + tig * 2;
            int h = n >> 6, d = n & 63;
            if (r1 < NTOK)
                *(float2*)&g_q[(((size_t)b * NHEADS + h) * NTOK + r1) * HD + d] =
                    make_float2(c[mt][nt][0], c[mt][nt][1]);
            if (r2 < NTOK)
                *(float2*)&g_q[(((size_t)b * NHEADS + h) * NTOK + r2) * HD + d] =
                    make_float2(c[mt][nt][2], c[mt][nt][3]);
        }
    }
}

__device__ __forceinline__ void conv_body(const float* __restrict__ xb,
                                          const float* __restrict__ Wsr,
                                          const float* __restrict__ b_sr,
                                          unsigned* As, unsigned* Bs,
                                          int b, int m0, int n0) {
    int tid = threadIdx.x, lane = tid & 31, warp = tid >> 5;
    int g = lane >> 2, tig = lane & 3;
    int wm = warp >> 1, wn = warp & 1;
    float c[2][8][4] = {};
    int kr = tid >> 5, c4 = (tid & 31) * 4;          // A rows kr, kr+8; m cols c4..c4+3
    int nrB = tid >> 1, k8B = (tid & 1) * 8;         // B: one n row, 8 k
    int moff[4]; bool mval[4];
#pragma unroll
    for (int q = 0; q < 4; q++) {
        int m = m0 + c4 + q;
        mval[q] = m < KTOK;
        int ph = m / 28, pw = m - ph * 28;
        moff[q] = mval[q] ? (2 * ph * FSZ + 2 * pw) : 0;
    }
    for (int k0 = 0; k0 < 2048; k0 += 16) {
        {
            int k = k0 + kr;
            int ii = k >> 2, kh = (k >> 1) & 1, kw = k & 1;
            const float* xp = xb + (size_t)ii * NTOK + kh * FSZ + kw;
            int k2 = k + 8;
            int ii2 = k2 >> 2, kh2 = (k2 >> 1) & 1, kw2 = k2 & 1;
            const float* xp2 = xb + (size_t)ii2 * NTOK + kh2 * FSZ + kw2;
#pragma unroll
            for (int q = 0; q < 4; q++) {
                As[kr * TPAD + c4 + q] = f2tf(mval[q] ? xp[moff[q]] : 0.f);
                As[(kr + 8) * TPAD + c4 + q] = f2tf(mval[q] ? xp2[moff[q]] : 0.f);
            }
            const float* wp = Wsr + (size_t)(n0 + nrB) * 2048 + k0 + k8B;
            float4 w0 = *(const float4*)wp, w1 = *(const float4*)(wp + 4);
            Bs[(k8B + 0) * TPAD + nrB] = f2tf(w0.x);
            Bs[(k8B + 1) * TPAD + nrB] = f2tf(w0.y);
            Bs[(k8B + 2) * TPAD + nrB] = f2tf(w0.z);
            Bs[(k8B + 3) * TPAD + nrB] = f2tf(w0.w);
            Bs[(k8B + 4) * TPAD + nrB] = f2tf(w1.x);
            Bs[(k8B + 5) * TPAD + nrB] = f2tf(w1.y);
            Bs[(k8B + 6) * TPAD + nrB] = f2tf(w1.z);
            Bs[(k8B + 7) * TPAD + nrB] = f2tf(w1.w);
        }
        __syncthreads();
        mma_tile16w(As, Bs, c, wm, wn, g, tig);
        __syncthreads();
    }
#pragma unroll
    for (int mt = 0; mt < 2; mt++) {
        int r1 = m0 + wm * 32 + mt * 16 + g, r2 = r1 + 8;
#pragma unroll
        for (int nt = 0; nt < 8; nt++) {
            int n = n0 + wn * 64 + nt * 8 + tig * 2;
            float2 bb = *(const float2*)&b_sr[n];
            if (r1 < KTOK)
                *(float2*)&g_xr[((size_t)b * KTOK + r1) * DIMC + n] =
                    make_float2(c[mt][nt][0] + bb.x, c[mt][nt][1] + bb.y);
            if (r2 < KTOK)
                *(float2*)&g_xr[((size_t)b * KTOK + r2) * DIMC + n] =
                    make_float2(c[mt][nt][2] + bb.x, c[mt][nt][3] + bb.y);
        }
    }
}

__global__ __launch_bounds__(256) void gemm_qc(const float* __restrict__ x,
                                               const float* __restrict__ Wq,
                                               const float* __restrict__ Wsr,
                                               const float* __restrict__ b_sr) {
    __shared__ unsigned As[16 * TPAD];
    __shared__ unsigned Bs[16 * TPAD];
    int b = blockIdx.z;
    const float* xb = x + (size_t)b * DIMC * NTOK;
    if (blockIdx.y < 25)
        q_body(xb, Wq, As, Bs, b, blockIdx.y * 128, blockIdx.x * 128);
    else
        conv_body(xb, Wsr, b_sr, As, Bs, b, (blockIdx.y - 25) * 128, blockIdx.x * 128);
}

// ---------------- LayerNorm ----------------
__global__ void ln_kernel(const float* __restrict__ gamma, const float* __restrict__ beta) {
    int row = blockIdx.x;
    float* p = g_xr + (long long)row * DIMC;
    int t = threadIdx.x;
    float v0 = p[t], v1 = p[t + 256];
    float s = v0 + v1, sq = v0 * v0 + v1 * v1;
#pragma unroll
    for (int o = 16; o > 0; o >>= 1) {
        s += __shfl_xor_sync(0xffffffffu, s, o);
        sq += __shfl_xor_sync(0xffffffffu, sq, o);
    }
    __shared__ float rs_[8], rq_[8];
    int lane = t & 31, w = t >> 5;
    if (lane == 0) { rs_[w] = s; rq_[w] = sq; }
    __syncthreads();
    if (t == 0) {
        float S = 0.f, Q = 0.f;
#pragma unroll
        for (int i = 0; i < 8; i++) { S += rs_[i]; Q += rq_[i]; }
        rs_[0] = S; rq_[0] = Q;
    }
    __syncthreads();
    float mu = rs_[0] * (1.f / 512.f);
    float var = rq_[0] * (1.f / 512.f) - mu * mu;
    float inv = rsqrtf(var + LN_EPS);
    p[t] = (v0 - mu) * inv * gamma[t] + beta[t];
    p[t + 256] = (v1 - mu) * inv * gamma[t + 256] + beta[t + 256];
}

// ---------------- GEMM KV (tf32): M=784, N=1024, K=512, 128x128 tiles ----------------
__global__ __launch_bounds__(256) void gemm_kv(const float* __restrict__ Wkv) {
    __shared__ unsigned As[16 * TPAD];
    __shared__ unsigned Bs[16 * TPAD];
    int b = blockIdx.z, m0 = blockIdx.y * 128, n0 = blockIdx.x * 128;
    int tid = threadIdx.x, lane = tid & 31, warp = tid >> 5;
    int g = lane >> 2, tig = lane & 3;
    int wm = warp >> 1, wn = warp & 1;
    const float* A = g_xr + (size_t)b * KTOK * DIMC;
    float c[2][8][4] = {};
    int mrA = tid >> 2, kc4A = (tid & 3) * 4;        // A: transpose rows mrA, mrA+64
    int krB = tid >> 5, c4B = (tid & 31) * 4;        // B rows krB, krB+8
    bool mv1 = (m0 + mrA) < KTOK, mv2 = (m0 + mrA + 64) < KTOK;
    for (int k0 = 0; k0 < DIMC; k0 += 16) {
        {
            const float* ap = A + (size_t)(m0 + mrA) * DIMC + k0 + kc4A;
            float4 a0 = mv1 ? *(const float4*)ap : make_float4(0, 0, 0, 0);
            float4 a1 = mv2 ? *(const float4*)(ap + 64 * (size_t)DIMC) : make_float4(0, 0, 0, 0);
            As[(kc4A + 0) * TPAD + mrA] = f2tf(a0.x);
            As[(kc4A + 1) * TPAD + mrA] = f2tf(a0.y);
            As[(kc4A + 2) * TPAD + mrA] = f2tf(a0.z);
            As[(kc4A + 3) * TPAD + mrA] = f2tf(a0.w);
            As[(kc4A + 0) * TPAD + mrA + 64] = f2tf(a1.x);
            As[(kc4A + 1) * TPAD + mrA + 64] = f2tf(a1.y);
            As[(kc4A + 2) * TPAD + mrA + 64] = f2tf(a1.z);
            As[(kc4A + 3) * TPAD + mrA + 64] = f2tf(a1.w);
            const float* bp = Wkv + (size_t)(k0 + krB) * 1024 + n0 + c4B;
            *(uint4*)&Bs[krB * TPAD + c4B] = tf4(*(const float4*)bp);
            *(uint4*)&Bs[(krB + 8) * TPAD + c4B] = tf4(*(const float4*)(bp + 8 * 1024));
        }
        __syncthreads();
        mma_tile16w(As, Bs, c, wm, wn, g, tig);
        __syncthreads();
    }
#pragma unroll
    for (int mt = 0; mt < 2; mt++) {
        int r1 = m0 + wm * 32 + mt * 16 + g, r2 = r1 + 8;
#pragma unroll
        for (int nt = 0; nt < 8; nt++) {
            int n = n0 + wn * 64 + nt * 8 + tig * 2;
            int d = n >> 4, h = (n >> 1) & 7;
            if (r1 < KTOK) {
                size_t dst = (((size_t)b * NHEADS + h) * KTOK + r1) * HD + d;
                g_k[dst] = c[mt][nt][0];
                g_v[dst] = c[mt][nt][1];
            }
            if (r2 < KTOK) {
                size_t dst = (((size_t)b * NHEADS + h) * KTOK + r2) * HD + d;
                g_k[dst] = c[mt][nt][2];
                g_v[dst] = c[mt][nt][3];
            }
        }
    }
}

// ---------------- fused attention (tf32 MMA flash) — R8, unchanged ----------------
__global__ __launch_bounds__(256, 2) void attn_kernel() {
    extern __shared__ __align__(16) unsigned smu[];
    unsigned* Ks = smu;                       // 112*68
    unsigned* Vs = smu + 7616;                // 112*72
    unsigned* Ps = Vs + 8064;                 // 64*132
    float* redm = (float*)(Ps + 8448);        // 128
    float* reds = redm + 128;                 // 128

    int bh = blockIdx.y, row0 = blockIdx.x * 64;
    int tid = threadIdx.x, lane = tid & 31, warp = tid >> 5;
    int g = lane >> 2, tig = lane & 3;
    int wm = warp & 3, wn = warp >> 2;

    const float* qb = g_q + (size_t)bh * NTOK * HD;
    const float* kb = g_k + (size_t)bh * KTOK * HD;
    const float* vb = g_v + (size_t)bh * KTOK * HD;

    int r1 = wm * 16 + g, r2 = r1 + 8;

    unsigned aq[8][4];
    {
        const float* q1 = qb + (size_t)(row0 + r1) * HD;
        const float* q2 = qb + (size_t)(row0 + r2) * HD;
#pragma unroll
        for (int ks = 0; ks < 8; ks++) {
            aq[ks][0] = f2tf(q1[ks * 8 + tig]);
            aq[ks][1] = f2tf(q2[ks * 8 + tig]);
            aq[ks][2] = f2tf(q1[ks * 8 + tig + 4]);
            aq[ks][3] = f2tf(q2[ks * 8 + tig + 4]);
        }
    }
    float run_max1 = -INFINITY, run_max2 = -INFINITY;
    float run_sum1 = 0.f, run_sum2 = 0.f;
    float c_o[4][4] = {};

    for (int t = 0; t < 7; t++) {
        int m0 = t * 112;
        __syncthreads();
        for (int e = tid; e < 112 * 16; e += 256) {
            int mr = e >> 4, d4 = (e & 15) * 4;
            float4 k4 = *(const float4*)&kb[(size_t)(m0 + mr) * HD + d4];
            unsigned* kd = &Ks[mr * 68 + d4];
            kd[0] = f2tf(k4.x); kd[1] = f2tf(k4.y); kd[2] = f2tf(k4.z); kd[3] = f2tf(k4.w);
            float4 v4 = *(const float4*)&vb[(size_t)(m0 + mr) * HD + d4];
            unsigned* vd = &Vs[mr * 72 + d4];
            vd[0] = f2tf(v4.x); vd[1] = f2tf(v4.y); vd[2] = f2tf(v4.z); vd[3] = f2tf(v4.w);
        }
        __syncthreads();

        float cs[7][4] = {};
#pragma unroll
        for (int ks = 0; ks < 8; ks++) {
#pragma unroll
            for (int nt = 0; nt < 7; nt++) {
                int n = wn * 56 + nt * 8 + g;
                unsigned bk[2];
                bk[0] = Ks[n * 68 + ks * 8 + tig];
                bk[1] = Ks[n * 68 + ks * 8 + tig + 4];
                MMA8(cs[nt], aq[ks], bk);
            }
        }
        float p1[14], p2[14];
        float mx1 = -INFINITY, mx2 = -INFINITY;
#pragma unroll
        for (int nt = 0; nt < 7; nt++) {
            int col = m0 + wn * 56 + nt * 8 + tig * 2;
            float2 b1 = *(const float2*)&g_bias[(size_t)(row0 + r1) * KTOK + col];
            float2 b2 = *(const float2*)&g_bias[(size_t)(row0 + r2) * KTOK + col];
            p1[2 * nt]     = cs[nt][0] * ATT_SCALE + b1.x;
            p1[2 * nt + 1] = cs[nt][1] * ATT_SCALE + b1.y;
            p2[2 * nt]     = cs[nt][2] * ATT_SCALE + b2.x;
            p2[2 * nt + 1] = cs[nt][3] * ATT_SCALE + b2.y;
            mx1 = fmaxf(mx1, fmaxf(p1[2 * nt], p1[2 * nt + 1]));
            mx2 = fmaxf(mx2, fmaxf(p2[2 * nt], p2[2 * nt + 1]));
        }
        mx1 = fmaxf(mx1, __shfl_xor_sync(0xffffffffu, mx1, 1));
        mx1 = fmaxf(mx1, __shfl_xor_sync(0xffffffffu, mx1, 2));
        mx2 = fmaxf(mx2, __shfl_xor_sync(0xffffffffu, mx2, 1));
        mx2 = fmaxf(mx2, __shfl_xor_sync(0xffffffffu, mx2, 2));
        if (tig == 0) { redm[wn * 64 + r1] = mx1; redm[wn * 64 + r2] = mx2; }
        __syncthreads();
        float tm1 = fmaxf(redm[r1], redm[64 + r1]);
        float tm2 = fmaxf(redm[r2], redm[64 + r2]);
        float nm1 = fmaxf(run_max1, tm1), nm2 = fmaxf(run_max2, tm2);
        float co1 = __expf(run_max1 - nm1), co2 = __expf(run_max2 - nm2);
        run_max1 = nm1; run_max2 = nm2;
        float s1 = 0.f, s2 = 0.f;
#pragma unroll
        for (int i = 0; i < 14; i++) {
            p1[i] = __expf(p1[i] - nm1); s1 += p1[i];
            p2[i] = __expf(p2[i] - nm2); s2 += p2[i];
        }
        s1 += __shfl_xor_sync(0xffffffffu, s1, 1);
        s1 += __shfl_xor_sync(0xffffffffu, s1, 2);
        s2 += __shfl_xor_sync(0xffffffffu, s2, 1);
        s2 += __shfl_xor_sync(0xffffffffu, s2, 2);
        if (tig == 0) { reds[wn * 64 + r1] = s1; reds[wn * 64 + r2] = s2; }
#pragma unroll
        for (int nt = 0; nt < 7; nt++) {
            int col = wn * 56 + nt * 8 + tig * 2;
            uint2 w1 = make_uint2(f2tf(p1[2 * nt]), f2tf(p1[2 * nt + 1]));
            uint2 w2 = make_uint2(f2tf(p2[2 * nt]), f2tf(p2[2 * nt + 1]));
            *(uint2*)&Ps[r1 * 132 + col] = w1;
            *(uint2*)&Ps[r2 * 132 + col] = w2;
        }
#pragma unroll
        for (int nt = 0; nt < 4; nt++) {
            c_o[nt][0] *= co1; c_o[nt][1] *= co1;
            c_o[nt][2] *= co2; c_o[nt][3] *= co2;
        }
        __syncthreads();
        run_sum1 = run_sum1 * co1 + reds[r1] + reds[64 + r1];
        run_sum2 = run_sum2 * co2 + reds[r2] + reds[64 + r2];
#pragma unroll
        for (int ks = 0; ks < 14; ks++) {
            unsigned ap[4];
            ap[0] = Ps[r1 * 132 + ks * 8 + tig];
            ap[1] = Ps[r2 * 132 + ks * 8 + tig];
            ap[2] = Ps[r1 * 132 + ks * 8 + tig + 4];
            ap[3] = Ps[r2 * 132 + ks * 8 + tig + 4];
#pragma unroll
            for (int nt = 0; nt < 4; nt++) {
                int n = wn * 32 + nt * 8 + g;
                unsigned bv[2];
                bv[0] = Vs[(ks * 8 + tig) * 72 + n];
                bv[1] = Vs[(ks * 8 + tig + 4) * 72 + n];
                MMA8(c_o[nt], ap, bv);
            }
        }
    }
    int b = bh >> 3, h = bh & 7;
    float i1 = 1.f / run_sum1, i2 = 1.f / run_sum2;
#pragma unroll
    for (int nt = 0; nt < 4; nt++) {
        int d = h * HD + wn * 32 + nt * 8 + tig * 2;
        *(float2*)&g_ao[((size_t)b * NTOK + row0 + r1) * DIMC + d] =
            make_float2(c_o[nt][0] * i1, c_o[nt][1] * i1);
        *(float2*)&g_ao[((size_t)b * NTOK + row0 + r2) * DIMC + d] =
            make_float2(c_o[nt][2] * i2, c_o[nt][3] * i2);
    }
}

// ---------------- GEMM out (tf32): [12544,512]@[512,512], 128x128 tiles ----------------
__global__ __launch_bounds__(256) void gemm_out(const float* __restrict__ Wp,
                                                const float* __restrict__ bp,
                                                float* __restrict__ out) {
    __shared__ unsigned As[16 * TPAD];
    __shared__ unsigned Bs[16 * TPAD];
    int m0 = blockIdx.y * 128, n0 = blockIdx.x * 128;
    int tid = threadIdx.x, lane = tid & 31, warp = tid >> 5;
    int g = lane >> 2, tig = lane & 3;
    int wm = warp >> 1, wn = warp & 1;
    float c[2][8][4] = {};
    int mrA = tid >> 2, kc4A = (tid & 3) * 4;
    int krB = tid >> 5, c4B = (tid & 31) * 4;
    for (int k0 = 0; k0 < DIMC; k0 += 16) {
        {
            const float* ap = g_ao + (size_t)(m0 + mrA) * DIMC + k0 + kc4A;
            float4 a0 = *(const float4*)ap;
            float4 a1 = *(const float4*)(ap + 64 * (size_t)DIMC);
            As[(kc4A + 0) * TPAD + mrA] = f2tf(a0.x);
            As[(kc4A + 1) * TPAD + mrA] = f2tf(a0.y);
            As[(kc4A + 2) * TPAD + mrA] = f2tf(a0.z);
            As[(kc4A + 3) * TPAD + mrA] = f2tf(a0.w);
            As[(kc4A + 0) * TPAD + mrA + 64] = f2tf(a1.x);
            As[(kc4A + 1) * TPAD + mrA + 64] = f2tf(a1.y);
            As[(kc4A + 2) * TPAD + mrA + 64] = f2tf(a1.z);
            As[(kc4A + 3) * TPAD + mrA + 64] = f2tf(a1.w);
            const float* bpw = Wp + (size_t)(k0 + krB) * DIMC + n0 + c4B;
            *(uint4*)&Bs[krB * TPAD + c4B] = tf4(*(const float4*)bpw);
            *(uint4*)&Bs[(krB + 8) * TPAD + c4B] = tf4(*(const float4*)(bpw + 8 * (size_t)DIMC));
        }
        __syncthreads();
        mma_tile16w(As, Bs, c, wm, wn, g, tig);
        __syncthreads();
    }
#pragma unroll
    for (int mt = 0; mt < 2; mt++) {
        int r1 = m0 + wm * 32 + mt * 16 + g, r2 = r1 + 8;
        int b1 = r1 / NTOK, n1 = r1 - b1 * NTOK;
        int b2 = r2 / NTOK, n2 = r2 - b2 * NTOK;
#pragma unroll
        for (int nt = 0; nt < 8; nt++) {
            int cc = n0 + wn * 64 + nt * 8 + tig * 2;
            float bb0 = bp[cc], bb1 = bp[cc + 1];
            out[((size_t)b1 * DIMC + cc) * NTOK + n1] = c[mt][nt][0] + bb0;
            out[((size_t)b1 * DIMC + cc + 1) * NTOK + n1] = c[mt][nt][1] + bb1;
            out[((size_t)b2 * DIMC + cc) * NTOK + n2] = c[mt][nt][2] + bb0;
            out[((size_t)b2 * DIMC + cc + 1) * NTOK + n2] = c[mt][nt][3] + bb1;
        }
    }
}

// ---------------- launch ----------------
extern "C" void kernel_launch(void* const* d_in, const int* in_sizes, int n_in,
                              void* d_out, int out_size) {
    const float* x     = (const float*)d_in[0];
    const float* Wq    = (const float*)d_in[1];
    const float* Wkv   = (const float*)d_in[2];
    const float* Wsr   = (const float*)d_in[3];
    const float* b_sr  = (const float*)d_in[4];
    const float* gamma = (const float*)d_in[5];
    const float* beta  = (const float*)d_in[6];
    const float* Wp    = (const float*)d_in[7];
    const float* bp    = (const float*)d_in[8];
    const float* pos   = (const float*)d_in[9];
    const int*   rel   = (const int*)d_in[10];
    float* out = (float*)d_out;

    const int ATT_SMEM = (7616 + 8064 + 8448 + 256) * 4;  // 97,536 B
    cudaFuncSetAttribute(attn_kernel, cudaFuncAttributeMaxDynamicSharedMemorySize, ATT_SMEM);

    bias_kernel<<<(NTOK * KTOK / 2 + 255) / 256, 256>>>(pos, rel);
    gemm_qc<<<dim3(4, 32, BATCH), 256>>>(x, Wq, Wsr, b_sr);
    ln_kernel<<<BATCH * KTOK, 256>>>(gamma, beta);
    gemm_kv<<<dim3(8, 7, BATCH), 256>>>(Wkv);
    attn_kernel<<<dim3(49, 32), 256, ATT_SMEM>>>();
    gemm_out<<<dim3(4, 98, 1), 256>>>(Wp, bp, out);
}